// round 5
// baseline (speedup 1.0000x reference)
#include <cuda_runtime.h>
#include <cuda_fp16.h>

#define N_NODES 50000
#define OUT_DIM 128
#define NNZ_X 800000
#define N_EDGES 1600000
#define CAP_X 64     // Poisson(16): P(row >= 64) ~ 1e-18
#define CAP_A 128    // Poisson(32): P(row >= 128) ~ 0

// ---- persistent scratch (__device__ globals; zero-initialized at load) ----
__device__ __half g_hh[N_NODES * OUT_DIM];        // 12.8 MB intermediate (fp16)
__device__ int    g_xcnt[N_NODES];                // self-cleaning counters
__device__ int    g_acnt[N_NODES];
__device__ int2   g_bx[N_NODES * CAP_X];          // 25.6 MB  {col, val bits}
__device__ int2   g_ba[N_NODES * CAP_A];          // 51.2 MB  {col, val bits}

// ---- 1: scatter into fixed-capacity row buckets (no hist/scan needed) ----
__global__ void scatter_kernel(const int4* __restrict__ x_rows4,
                               const int4* __restrict__ x_cols4,
                               const float4* __restrict__ x_vals4,
                               const float4* __restrict__ noise4,
                               const int4* __restrict__ adj_rows4,
                               const int4* __restrict__ adj_cols4,
                               const float4* __restrict__ adj_vals4) {
    int idx = blockIdx.x * blockDim.x + threadIdx.x;
    int stride = gridDim.x * blockDim.x;
    for (int i = idx; i < NNZ_X / 4; i += stride) {
        int4 r = x_rows4[i];
        int4 c = x_cols4[i];
        float4 v = x_vals4[i];
        float4 n = noise4[i];
        v.x *= floorf(1.0f + n.x);   // keep_prob=1 -> mask==1 (faithful to ref)
        v.y *= floorf(1.0f + n.y);
        v.z *= floorf(1.0f + n.z);
        v.w *= floorf(1.0f + n.w);
        int p0 = atomicAdd(&g_xcnt[r.x], 1);
        int p1 = atomicAdd(&g_xcnt[r.y], 1);
        int p2 = atomicAdd(&g_xcnt[r.z], 1);
        int p3 = atomicAdd(&g_xcnt[r.w], 1);
        if (p0 < CAP_X) g_bx[r.x * CAP_X + p0] = make_int2(c.x, __float_as_int(v.x));
        if (p1 < CAP_X) g_bx[r.y * CAP_X + p1] = make_int2(c.y, __float_as_int(v.y));
        if (p2 < CAP_X) g_bx[r.z * CAP_X + p2] = make_int2(c.z, __float_as_int(v.z));
        if (p3 < CAP_X) g_bx[r.w * CAP_X + p3] = make_int2(c.w, __float_as_int(v.w));
    }
    for (int i = idx; i < N_EDGES / 4; i += stride) {
        int4 r = adj_rows4[i];
        int4 c = adj_cols4[i];
        float4 v = adj_vals4[i];
        int p0 = atomicAdd(&g_acnt[r.x], 1);
        int p1 = atomicAdd(&g_acnt[r.y], 1);
        int p2 = atomicAdd(&g_acnt[r.z], 1);
        int p3 = atomicAdd(&g_acnt[r.w], 1);
        if (p0 < CAP_A) g_ba[r.x * CAP_A + p0] = make_int2(c.x, __float_as_int(v.x));
        if (p1 < CAP_A) g_ba[r.y * CAP_A + p1] = make_int2(c.y, __float_as_int(v.y));
        if (p2 < CAP_A) g_ba[r.z * CAP_A + p2] = make_int2(c.z, __float_as_int(v.z));
        if (p3 < CAP_A) g_ba[r.w * CAP_A + p3] = make_int2(c.w, __float_as_int(v.w));
    }
}

// ---- 2: hop1  h[row] = sum v * W[col]  -> fp16 store (warp per row) ----
__global__ void hop1_kernel(const float4* __restrict__ W4) {
    int row = (blockIdx.x * blockDim.x + threadIdx.x) >> 5;
    int lane = threadIdx.x & 31;
    if (row >= N_NODES) return;
    int n = g_xcnt[row];                 // broadcast load
    __syncwarp();
    if (lane == 0) g_xcnt[row] = 0;      // self-clean for next replay
    n = min(n, CAP_X);
    const int2* __restrict__ e = g_bx + row * CAP_X;
    float4 acc = make_float4(0.f, 0.f, 0.f, 0.f);
    int i = 0;
    for (; i + 4 <= n; i += 4) {
        int2 e0 = e[i], e1 = e[i + 1], e2 = e[i + 2], e3 = e[i + 3];
        float4 w0 = W4[e0.x * 32 + lane];
        float4 w1 = W4[e1.x * 32 + lane];
        float4 w2 = W4[e2.x * 32 + lane];
        float4 w3 = W4[e3.x * 32 + lane];
        float v0 = __int_as_float(e0.y), v1 = __int_as_float(e1.y);
        float v2 = __int_as_float(e2.y), v3 = __int_as_float(e3.y);
        acc.x += v0 * w0.x + v1 * w1.x + v2 * w2.x + v3 * w3.x;
        acc.y += v0 * w0.y + v1 * w1.y + v2 * w2.y + v3 * w3.y;
        acc.z += v0 * w0.z + v1 * w1.z + v2 * w2.z + v3 * w3.z;
        acc.w += v0 * w0.w + v1 * w1.w + v2 * w2.w + v3 * w3.w;
    }
    for (; i < n; i++) {
        int2 ee = e[i];
        float v = __int_as_float(ee.y);
        float4 w = W4[ee.x * 32 + lane];
        acc.x += v * w.x; acc.y += v * w.y; acc.z += v * w.z; acc.w += v * w.w;
    }
    __half2 lo = __floats2half2_rn(acc.x, acc.y);
    __half2 hi = __floats2half2_rn(acc.z, acc.w);
    uint2 u;
    u.x = *reinterpret_cast<unsigned*>(&lo);
    u.y = *reinterpret_cast<unsigned*>(&hi);
    reinterpret_cast<uint2*>(g_hh)[row * 32 + lane] = u;
}

// ---- 3: hop2  out[row] = relu(sum w * h_fp16[col])  (warp per row) ----
__device__ __forceinline__ void fma_h(float4& acc, float v, uint2 u) {
    __half2 lo = *reinterpret_cast<__half2*>(&u.x);
    __half2 hi = *reinterpret_cast<__half2*>(&u.y);
    float2 f0 = __half22float2(lo);
    float2 f1 = __half22float2(hi);
    acc.x += v * f0.x; acc.y += v * f0.y;
    acc.z += v * f1.x; acc.w += v * f1.y;
}

__global__ void hop2_kernel(float4* __restrict__ out4) {
    int row = (blockIdx.x * blockDim.x + threadIdx.x) >> 5;
    int lane = threadIdx.x & 31;
    if (row >= N_NODES) return;
    int n = g_acnt[row];                 // broadcast load
    __syncwarp();
    if (lane == 0) g_acnt[row] = 0;      // self-clean for next replay
    n = min(n, CAP_A);
    const int2* __restrict__ e = g_ba + row * CAP_A;
    const uint2* __restrict__ h2 = reinterpret_cast<const uint2*>(g_hh);
    float4 acc = make_float4(0.f, 0.f, 0.f, 0.f);
    int i = 0;
    for (; i + 8 <= n; i += 8) {
        int2 ee[8];
        uint2 u[8];
#pragma unroll
        for (int k = 0; k < 8; k++) ee[k] = e[i + k];
#pragma unroll
        for (int k = 0; k < 8; k++) u[k] = h2[ee[k].x * 32 + lane];
#pragma unroll
        for (int k = 0; k < 8; k++) fma_h(acc, __int_as_float(ee[k].y), u[k]);
    }
    for (; i < n; i++) {
        int2 ee = e[i];
        fma_h(acc, __int_as_float(ee.y), h2[ee.x * 32 + lane]);
    }
    acc.x = fmaxf(acc.x, 0.f); acc.y = fmaxf(acc.y, 0.f);
    acc.z = fmaxf(acc.z, 0.f); acc.w = fmaxf(acc.w, 0.f);
    out4[row * 32 + lane] = acc;
}

extern "C" void kernel_launch(void* const* d_in, const int* in_sizes, int n_in,
                              void* d_out, int out_size) {
    const int*   x_rows   = (const int*)d_in[0];
    const int*   x_cols   = (const int*)d_in[1];
    const float* x_vals   = (const float*)d_in[2];
    const float* noise    = (const float*)d_in[3];
    const int*   adj_rows = (const int*)d_in[4];
    const int*   adj_cols = (const int*)d_in[5];
    const float* adj_vals = (const float*)d_in[6];
    const float* W        = (const float*)d_in[7];
    float4* out4 = (float4*)d_out;

    scatter_kernel<<<1184, 256>>>((const int4*)x_rows, (const int4*)x_cols,
                                  (const float4*)x_vals, (const float4*)noise,
                                  (const int4*)adj_rows, (const int4*)adj_cols,
                                  (const float4*)adj_vals);

    hop1_kernel<<<(N_NODES * 32 + 255) / 256, 256>>>(reinterpret_cast<const float4*>(W));
    hop2_kernel<<<(N_NODES * 32 + 255) / 256, 256>>>(out4);
}

// round 6
// speedup vs baseline: 1.0869x; 1.0869x over previous
#include <cuda_runtime.h>
#include <cuda_fp16.h>

#define N_NODES 50000
#define OUT_DIM 128
#define NNZ_X 800000
#define N_EDGES 1600000

// ---- persistent scratch (__device__ globals; zero-initialized at load) ----
__device__ __half g_hh[N_NODES * OUT_DIM];           // 12.8 MB intermediate (fp16)
__device__ int   g_xcnt[N_NODES];                     // zero at entry of every call
__device__ int   g_acnt[N_NODES];                     // (self-cleaned by scan)
__device__ int   g_xstart[N_NODES + 1];
__device__ int   g_astart[N_NODES + 1];
__device__ int   g_xcur[N_NODES];
__device__ int   g_acur[N_NODES];
__device__ int2  g_xs[NNZ_X];                         // 6.4 MB  {col, val bits}
__device__ int2  g_as[N_EDGES];                       // 12.8 MB {col, val bits}

// ---- 1: histogram rows (counters were zeroed by previous call's scan) ----
__global__ void hist_kernel(const int4* __restrict__ x_rows4,
                            const int4* __restrict__ adj_rows4) {
    int idx = blockIdx.x * blockDim.x + threadIdx.x;
    int stride = gridDim.x * blockDim.x;
    for (int i = idx; i < NNZ_X / 8; i += stride) {
        int4 a = x_rows4[2 * i], b = x_rows4[2 * i + 1];
        atomicAdd(&g_xcnt[a.x], 1); atomicAdd(&g_xcnt[a.y], 1);
        atomicAdd(&g_xcnt[a.z], 1); atomicAdd(&g_xcnt[a.w], 1);
        atomicAdd(&g_xcnt[b.x], 1); atomicAdd(&g_xcnt[b.y], 1);
        atomicAdd(&g_xcnt[b.z], 1); atomicAdd(&g_xcnt[b.w], 1);
    }
    for (int i = idx; i < N_EDGES / 8; i += stride) {
        int4 a = adj_rows4[2 * i], b = adj_rows4[2 * i + 1];
        atomicAdd(&g_acnt[a.x], 1); atomicAdd(&g_acnt[a.y], 1);
        atomicAdd(&g_acnt[a.z], 1); atomicAdd(&g_acnt[a.w], 1);
        atomicAdd(&g_acnt[b.x], 1); atomicAdd(&g_acnt[b.y], 1);
        atomicAdd(&g_acnt[b.z], 1); atomicAdd(&g_acnt[b.w], 1);
    }
}

// ---- 2: exclusive scan; 2 blocks, one per histogram; self-cleans cnt ----
#define SCAN_T 1024
#define CHUNK 49   // 1024*49 >= 50000

__device__ __forceinline__ void scan_one(int* __restrict__ cnt,
                                         int* __restrict__ start,
                                         int* __restrict__ cur,
                                         int* wsum) {
    int t = threadIdx.x;
    int lane = t & 31, wid = t >> 5;
    int lo = t * CHUNK;
    int hi = min(lo + CHUNK, N_NODES);
    int sum = 0;
    for (int i = lo; i < hi; i++) sum += cnt[i];
    // warp-shuffle inclusive scan of per-thread sums
    int v = sum;
#pragma unroll
    for (int d = 1; d < 32; d <<= 1) {
        int u = __shfl_up_sync(0xffffffffu, v, d);
        if (lane >= d) v += u;
    }
    if (lane == 31) wsum[wid] = v;
    __syncthreads();
    if (wid == 0) {
        int w = wsum[lane];
#pragma unroll
        for (int d = 1; d < 32; d <<= 1) {
            int u = __shfl_up_sync(0xffffffffu, w, d);
            if (lane >= d) w += u;
        }
        wsum[lane] = w;
    }
    __syncthreads();
    int off = v - sum + (wid > 0 ? wsum[wid - 1] : 0);   // exclusive prefix
    for (int i = lo; i < hi; i++) {
        start[i] = off;
        cur[i] = off;
        off += cnt[i];
        cnt[i] = 0;                                      // self-clean for next replay
    }
    if (t == SCAN_T - 1) start[N_NODES] = off;           // lo>=N_NODES -> off == total
}

__global__ void scan_kernel() {
    __shared__ int wsum[32];
    if (blockIdx.x == 0) scan_one(g_xcnt, g_xstart, g_xcur, wsum);
    else                 scan_one(g_acnt, g_astart, g_acur, wsum);
}

// ---- 3: scatter into row-sorted order (8 outstanding ATOMGs per thread) ----
__global__ void scatter_kernel(const int4* __restrict__ x_rows4,
                               const int4* __restrict__ x_cols4,
                               const float4* __restrict__ x_vals4,
                               const float4* __restrict__ noise4,
                               const int4* __restrict__ adj_rows4,
                               const int4* __restrict__ adj_cols4,
                               const float4* __restrict__ adj_vals4) {
    int idx = blockIdx.x * blockDim.x + threadIdx.x;
    int stride = gridDim.x * blockDim.x;
    for (int i = idx; i < NNZ_X / 8; i += stride) {
        int4 r0 = x_rows4[2 * i],  r1 = x_rows4[2 * i + 1];
        int4 c0 = x_cols4[2 * i],  c1 = x_cols4[2 * i + 1];
        float4 v0 = x_vals4[2 * i], v1 = x_vals4[2 * i + 1];
        float4 n0 = noise4[2 * i],  n1 = noise4[2 * i + 1];
        v0.x *= floorf(1.0f + n0.x); v0.y *= floorf(1.0f + n0.y);
        v0.z *= floorf(1.0f + n0.z); v0.w *= floorf(1.0f + n0.w);
        v1.x *= floorf(1.0f + n1.x); v1.y *= floorf(1.0f + n1.y);
        v1.z *= floorf(1.0f + n1.z); v1.w *= floorf(1.0f + n1.w);
        int p0 = atomicAdd(&g_xcur[r0.x], 1);
        int p1 = atomicAdd(&g_xcur[r0.y], 1);
        int p2 = atomicAdd(&g_xcur[r0.z], 1);
        int p3 = atomicAdd(&g_xcur[r0.w], 1);
        int p4 = atomicAdd(&g_xcur[r1.x], 1);
        int p5 = atomicAdd(&g_xcur[r1.y], 1);
        int p6 = atomicAdd(&g_xcur[r1.z], 1);
        int p7 = atomicAdd(&g_xcur[r1.w], 1);
        g_xs[p0] = make_int2(c0.x, __float_as_int(v0.x));
        g_xs[p1] = make_int2(c0.y, __float_as_int(v0.y));
        g_xs[p2] = make_int2(c0.z, __float_as_int(v0.z));
        g_xs[p3] = make_int2(c0.w, __float_as_int(v0.w));
        g_xs[p4] = make_int2(c1.x, __float_as_int(v1.x));
        g_xs[p5] = make_int2(c1.y, __float_as_int(v1.y));
        g_xs[p6] = make_int2(c1.z, __float_as_int(v1.z));
        g_xs[p7] = make_int2(c1.w, __float_as_int(v1.w));
    }
    for (int i = idx; i < N_EDGES / 8; i += stride) {
        int4 r0 = adj_rows4[2 * i],  r1 = adj_rows4[2 * i + 1];
        int4 c0 = adj_cols4[2 * i],  c1 = adj_cols4[2 * i + 1];
        float4 v0 = adj_vals4[2 * i], v1 = adj_vals4[2 * i + 1];
        int p0 = atomicAdd(&g_acur[r0.x], 1);
        int p1 = atomicAdd(&g_acur[r0.y], 1);
        int p2 = atomicAdd(&g_acur[r0.z], 1);
        int p3 = atomicAdd(&g_acur[r0.w], 1);
        int p4 = atomicAdd(&g_acur[r1.x], 1);
        int p5 = atomicAdd(&g_acur[r1.y], 1);
        int p6 = atomicAdd(&g_acur[r1.z], 1);
        int p7 = atomicAdd(&g_acur[r1.w], 1);
        g_as[p0] = make_int2(c0.x, __float_as_int(v0.x));
        g_as[p1] = make_int2(c0.y, __float_as_int(v0.y));
        g_as[p2] = make_int2(c0.z, __float_as_int(v0.z));
        g_as[p3] = make_int2(c0.w, __float_as_int(v0.w));
        g_as[p4] = make_int2(c1.x, __float_as_int(v1.x));
        g_as[p5] = make_int2(c1.y, __float_as_int(v1.y));
        g_as[p6] = make_int2(c1.z, __float_as_int(v1.z));
        g_as[p7] = make_int2(c1.w, __float_as_int(v1.w));
    }
}

// ---- 4: hop1  h[row] = sum v * W[col]  -> fp16 store (warp per row) ----
__global__ void hop1_kernel(const float4* __restrict__ W4) {
    int row = (blockIdx.x * blockDim.x + threadIdx.x) >> 5;
    int lane = threadIdx.x & 31;
    if (row >= N_NODES) return;
    int s0 = g_xstart[row], s1 = g_xstart[row + 1];
    float4 acc = make_float4(0.f, 0.f, 0.f, 0.f);
    int i = s0;
    for (; i + 4 <= s1; i += 4) {
        int2 e0 = g_xs[i], e1 = g_xs[i + 1], e2 = g_xs[i + 2], e3 = g_xs[i + 3];
        float4 w0 = W4[e0.x * 32 + lane];
        float4 w1 = W4[e1.x * 32 + lane];
        float4 w2 = W4[e2.x * 32 + lane];
        float4 w3 = W4[e3.x * 32 + lane];
        float v0 = __int_as_float(e0.y), v1 = __int_as_float(e1.y);
        float v2 = __int_as_float(e2.y), v3 = __int_as_float(e3.y);
        acc.x += v0 * w0.x + v1 * w1.x + v2 * w2.x + v3 * w3.x;
        acc.y += v0 * w0.y + v1 * w1.y + v2 * w2.y + v3 * w3.y;
        acc.z += v0 * w0.z + v1 * w1.z + v2 * w2.z + v3 * w3.z;
        acc.w += v0 * w0.w + v1 * w1.w + v2 * w2.w + v3 * w3.w;
    }
    for (; i < s1; i++) {
        int2 e = g_xs[i];
        float v = __int_as_float(e.y);
        float4 w = W4[e.x * 32 + lane];
        acc.x += v * w.x; acc.y += v * w.y; acc.z += v * w.z; acc.w += v * w.w;
    }
    __half2 lo = __floats2half2_rn(acc.x, acc.y);
    __half2 hi = __floats2half2_rn(acc.z, acc.w);
    uint2 u;
    u.x = *reinterpret_cast<unsigned*>(&lo);
    u.y = *reinterpret_cast<unsigned*>(&hi);
    reinterpret_cast<uint2*>(g_hh)[row * 32 + lane] = u;
}

// ---- 5: hop2  out[row] = relu(sum w * h_fp16[col])  (warp per row) ----
__device__ __forceinline__ void fma_h(float4& acc, float v, uint2 u) {
    __half2 lo = *reinterpret_cast<__half2*>(&u.x);
    __half2 hi = *reinterpret_cast<__half2*>(&u.y);
    float2 f0 = __half22float2(lo);
    float2 f1 = __half22float2(hi);
    acc.x += v * f0.x; acc.y += v * f0.y;
    acc.z += v * f1.x; acc.w += v * f1.y;
}

__global__ void hop2_kernel(float4* __restrict__ out4) {
    int row = (blockIdx.x * blockDim.x + threadIdx.x) >> 5;
    int lane = threadIdx.x & 31;
    if (row >= N_NODES) return;
    int s0 = g_astart[row], s1 = g_astart[row + 1];
    const uint2* __restrict__ h2 = reinterpret_cast<const uint2*>(g_hh);
    float4 acc = make_float4(0.f, 0.f, 0.f, 0.f);
    int i = s0;
    for (; i + 8 <= s1; i += 8) {
        int2 e[8];
        uint2 u[8];
#pragma unroll
        for (int k = 0; k < 8; k++) e[k] = g_as[i + k];
#pragma unroll
        for (int k = 0; k < 8; k++) u[k] = h2[e[k].x * 32 + lane];
#pragma unroll
        for (int k = 0; k < 8; k++) fma_h(acc, __int_as_float(e[k].y), u[k]);
    }
    for (; i < s1; i++) {
        int2 e = g_as[i];
        fma_h(acc, __int_as_float(e.y), h2[e.x * 32 + lane]);
    }
    acc.x = fmaxf(acc.x, 0.f); acc.y = fmaxf(acc.y, 0.f);
    acc.z = fmaxf(acc.z, 0.f); acc.w = fmaxf(acc.w, 0.f);
    out4[row * 32 + lane] = acc;
}

extern "C" void kernel_launch(void* const* d_in, const int* in_sizes, int n_in,
                              void* d_out, int out_size) {
    const int*   x_rows   = (const int*)d_in[0];
    const int*   x_cols   = (const int*)d_in[1];
    const float* x_vals   = (const float*)d_in[2];
    const float* noise    = (const float*)d_in[3];
    const int*   adj_rows = (const int*)d_in[4];
    const int*   adj_cols = (const int*)d_in[5];
    const float* adj_vals = (const float*)d_in[6];
    const float* W        = (const float*)d_in[7];
    float4* out4 = (float4*)d_out;

    hist_kernel<<<1184, 256>>>((const int4*)x_rows, (const int4*)adj_rows);
    scan_kernel<<<2, SCAN_T>>>();
    scatter_kernel<<<1184, 256>>>((const int4*)x_rows, (const int4*)x_cols,
                                  (const float4*)x_vals, (const float4*)noise,
                                  (const int4*)adj_rows, (const int4*)adj_cols,
                                  (const float4*)adj_vals);

    hop1_kernel<<<(N_NODES * 32 + 255) / 256, 256>>>(reinterpret_cast<const float4*>(W));
    hop2_kernel<<<(N_NODES * 32 + 255) / 256, 256>>>(out4);
}